// round 5
// baseline (speedup 1.0000x reference)
#include <cuda_runtime.h>

#define LSEQ   2048
#define DMODEL 512
#define NHEAD  8
#define DH     64
#define BATCH  2
#define BH     (BATCH * NHEAD)   /* 16 */
#define MROWS  (BATCH * LSEQ)    /* 4096 */
#define SHIFT  48.0f

typedef unsigned long long ull;

// ---------------- packed f32x2 helpers ----------------
__device__ __forceinline__ ull pack2(float lo, float hi) {
    ull r; asm("mov.b64 %0, {%1, %2};" : "=l"(r) : "f"(lo), "f"(hi)); return r;
}
__device__ __forceinline__ ull dup2(float x) {
    ull r; asm("mov.b64 %0, {%1, %1};" : "=l"(r) : "f"(x)); return r;
}
__device__ __forceinline__ void unpack2(ull v, float& lo, float& hi) {
    asm("mov.b64 {%0, %1}, %2;" : "=f"(lo), "=f"(hi) : "l"(v));
}
__device__ __forceinline__ ull fma2(ull a, ull b, ull c) {
    ull d; asm("fma.rn.f32x2 %0, %1, %2, %3;" : "=l"(d) : "l"(a), "l"(b), "l"(c)); return d;
}
__device__ __forceinline__ ull add2(ull a, ull b) {
    ull d; asm("add.rn.f32x2 %0, %1, %2;" : "=l"(d) : "l"(a), "l"(b)); return d;
}
__device__ __forceinline__ ull mul2(ull a, ull b) {
    ull d; asm("mul.rn.f32x2 %0, %1, %2;" : "=l"(d) : "l"(a), "l"(b)); return d;
}

// ---------------- scratch ----------------
__device__ float g_qh[BH * LSEQ * DH];
__device__ float g_kh[BH * LSEQ * DH];
__device__ float g_vh[BH * LSEQ * DH];
__device__ float g_att[MROWS * DMODEL];
__device__ float g_rowsum[BH * LSEQ];

// ---------------------------------------------------------------------------
// 64x64-tiled GEMM with f32x2 inner math: C[4096,512] = A @ W + bias
// qkv=1: blockIdx.z selects (q,k,v) projection; writes transposed-head layout.
// qkv=0: single plain GEMM (final projection).
// ---------------------------------------------------------------------------
__global__ __launch_bounds__(256) void gemm512(const float* __restrict__ A0,
                                               const float* __restrict__ W0,
                                               const float* __restrict__ b0,
                                               float* __restrict__ o0,
                                               const float* __restrict__ A1,
                                               const float* __restrict__ W1,
                                               const float* __restrict__ b1,
                                               float* __restrict__ o1,
                                               const float* __restrict__ A2,
                                               const float* __restrict__ W2,
                                               const float* __restrict__ b2,
                                               float* __restrict__ o2,
                                               int head_layout)
{
    const float* A = A0; const float* W = W0; const float* bias = b0; float* out = o0;
    if (blockIdx.z == 1) { A = A1; W = W1; bias = b1; out = o1; }
    if (blockIdx.z == 2) { A = A2; W = W2; bias = b2; out = o2; }

    __shared__ float As[64 * 16];
    __shared__ float Ws[16 * 64];
    const int tid = threadIdx.x;
    const int tx = tid & 15, ty = tid >> 4;
    const int m0 = blockIdx.x * 64;
    const int n0 = blockIdx.y * 64;

    ull acc2[4][2] = {};

    for (int k0 = 0; k0 < DMODEL; k0 += 16) {
        {
            int idx = tid * 4;
            int r = idx >> 4, c = idx & 15;
            *(float4*)(As + idx) =
                *(const float4*)(A + (size_t)(m0 + r) * DMODEL + k0 + c);
            int kk = idx >> 6, cc = idx & 63;
            *(float4*)(Ws + idx) =
                *(const float4*)(W + (size_t)(k0 + kk) * DMODEL + n0 + cc);
        }
        __syncthreads();
#pragma unroll
        for (int kk = 0; kk < 16; kk++) {
            ulonglong2 bp = *(const ulonglong2*)(Ws + kk * 64 + tx * 4);
#pragma unroll
            for (int u = 0; u < 4; u++) {
                ull ad = dup2(As[(ty * 4 + u) * 16 + kk]);
                acc2[u][0] = fma2(ad, bp.x, acc2[u][0]);
                acc2[u][1] = fma2(ad, bp.y, acc2[u][1]);
            }
        }
        __syncthreads();
    }

    float4 bb = *(const float4*)(bias + n0 + tx * 4);

#pragma unroll
    for (int u = 0; u < 4; u++) {
        int m = m0 + ty * 4 + u;
        float4 o;
        unpack2(acc2[u][0], o.x, o.y);
        unpack2(acc2[u][1], o.z, o.w);
        o.x += bb.x; o.y += bb.y; o.z += bb.z; o.w += bb.w;
        if (head_layout) {
            int b = m >> 11;
            int l = m & (LSEQ - 1);
            int h = n0 >> 6;
            float* p = out + (((size_t)(b * NHEAD + h) * LSEQ + l) * DH + tx * 4);
            *(float4*)p = o;
        } else {
            *(float4*)(out + (size_t)m * DMODEL + n0 + tx * 4) = o;
        }
    }
}

// ---------------------------------------------------------------------------
// Fused causal attention, f32x2 math, 512 threads, 4x8 frags on 128x128 tiles.
// Smem layouts identical to R4 (205KB, 1 CTA/SM, now 16 warps).
// ---------------------------------------------------------------------------
#define QT_OFF 0
#define KB_OFF 8448
#define WB_OFF 17152
#define PS_OFF 34560
#define SMEM_FLOATS 51456
#define SMEM_BYTES (SMEM_FLOATS * 4)

__global__ __launch_bounds__(512, 1) void attn_kernel(const float* __restrict__ qh,
                                                      const float* __restrict__ kh,
                                                      const float* __restrict__ vh,
                                                      const float* __restrict__ key_rel,
                                                      const float* __restrict__ val_rel,
                                                      float* __restrict__ aw,
                                                      float* __restrict__ att,
                                                      float* __restrict__ rowsum,
                                                      int write_aw)
{
    extern __shared__ float sm[];
    float* QT = sm + QT_OFF;
    float* KT = sm + KB_OFF;   // aliases VS
    float* VS = sm + KB_OFF;
    float* WT = sm + WB_OFF;   // aliases WV
    float* WV = sm + WB_OFF;
    float* Ps = sm + PS_OFF;

    const int tid = threadIdx.x;
    const int tx = tid & 15, ty = tid >> 4;        // ty in [0,32)
    const int ib = 15 - blockIdx.x;                // heavy blocks first
    const int i0 = ib * 128;
    const int bh = blockIdx.y;
    const int ntiles = ib + 1;

    // ---- QT fill (transpose): QT[d][i] ----
    const float* qbase = qh + ((size_t)bh * LSEQ + i0) * DH;
#pragma unroll
    for (int k = 0; k < 4; k++) {
        int idx = tid + k * 512;          // 2048 float4 groups
        int i = idx & 127, d4 = idx >> 7;
        float4 t = *(const float4*)(qbase + i * 64 + d4 * 4);
        QT[(4 * d4 + 0) * 132 + i] = t.x;
        QT[(4 * d4 + 1) * 132 + i] = t.y;
        QT[(4 * d4 + 2) * 132 + i] = t.z;
        QT[(4 * d4 + 3) * 132 + i] = t.w;
    }

    float rs[4];
    ull Co[4][2];
#pragma unroll
    for (int u = 0; u < 4; u++) { rs[u] = 0.f; Co[u][0] = 0; Co[u][1] = 0; }

    for (int t = 0; t < ntiles; t++) {
        const int j0 = t * 128;
        const int D0 = i0 - j0 - 127;

        __syncthreads();   // prior PV reads done (and QT fill on first iter)

        // ---- KT fill (transpose) ----
        const float* kbase = kh + ((size_t)bh * LSEQ + j0) * DH;
#pragma unroll
        for (int k = 0; k < 4; k++) {
            int idx = tid + k * 512;
            int j = idx & 127, d4 = idx >> 7;
            float4 tt = *(const float4*)(kbase + j * 64 + d4 * 4);
            KT[(4 * d4 + 0) * 132 + j] = tt.x;
            KT[(4 * d4 + 1) * 132 + j] = tt.y;
            KT[(4 * d4 + 2) * 132 + j] = tt.z;
            KT[(4 * d4 + 3) * 132 + j] = tt.w;
        }
        // ---- WT fill: WT[d][si], si = s+1, delta = si-1+D0 ----
#pragma unroll
        for (int k = 0; k < 8; k++) {
            int idx = tid + k * 512;      // 0..4095
            int si = idx & 255, d4 = idx >> 8;
            int delta = si - 1 + D0;
            float4 tt = make_float4(0.f, 0.f, 0.f, 0.f);
            if (delta >= 0 && delta < LSEQ)
                tt = *(const float4*)(key_rel + (size_t)(LSEQ - 1 - delta) * DH + d4 * 4);
            WT[(4 * d4 + 0) * 260 + si] = tt.x;
            WT[(4 * d4 + 1) * 260 + si] = tt.y;
            WT[(4 * d4 + 2) * 260 + si] = tt.z;
            WT[(4 * d4 + 3) * 260 + si] = tt.w;
        }
        __syncthreads();

        // ---- S compute: Sp[uu][v], uu packs rows (4ty+2uu, 4ty+2uu+1) ----
        ull Sp[2][8] = {};
        const float* qp = QT + 4 * ty;
        const float* kp = KT + 8 * tx;
        const float* wp = WT + (120 + 4 * ty - 8 * tx);

#pragma unroll 2
        for (int d = 0; d < 64; d++) {
            ulonglong2 aL = *(const ulonglong2*)qp;   // rows 4ty..4ty+3
            ull ap[2] = { aL.x, aL.y };

            float4 b0 = *(const float4*)kp;
            float4 b1 = *(const float4*)(kp + 4);
            ull bd[8] = { dup2(b0.x), dup2(b0.y), dup2(b0.z), dup2(b0.w),
                          dup2(b1.x), dup2(b1.y), dup2(b1.z), dup2(b1.w) };

            float4 w0 = *(const float4*)wp;
            float4 w1 = *(const float4*)(wp + 4);
            float4 w2 = *(const float4*)(wp + 8);
            float wv[12] = { w0.x, w0.y, w0.z, w0.w,
                             w1.x, w1.y, w1.z, w1.w,
                             w2.x, w2.y, w2.z, w2.w };
            ull P[11];
#pragma unroll
            for (int o = 1; o <= 10; o++) P[o] = pack2(wv[o], wv[o + 1]);

#pragma unroll
            for (int uu = 0; uu < 2; uu++) {
#pragma unroll
                for (int v = 0; v < 8; v++) {
                    Sp[uu][v] = fma2(ap[uu], bd[v], Sp[uu][v]);
                    Sp[uu][v] = fma2(ap[uu], P[8 + 2 * uu - v], Sp[uu][v]);
                }
            }
            qp += 132; kp += 132; wp += 260;
        }

        // ---- exp, mask, rowsum, Ps + aw stores ----
#pragma unroll
        for (int uu = 0; uu < 2; uu++) {
            const int iA = i0 + 4 * ty + 2 * uu;
            const int iB = iA + 1;
            float e0[8], e1[8];
#pragma unroll
            for (int v = 0; v < 8; v++) {
                float sA, sB;
                unpack2(Sp[uu][v], sA, sB);
                const int j = j0 + 8 * tx + v;
                e0[v] = (j <= iA) ? __expf(sA - SHIFT) : 0.f;
                e1[v] = (j <= iB) ? __expf(sB - SHIFT) : 0.f;
                rs[2 * uu]     += e0[v];
                rs[2 * uu + 1] += e1[v];
            }
            float* pr0 = Ps + (4 * ty + 2 * uu) * 132 + 8 * tx;
            float* pr1 = pr0 + 132;
            *(float4*)(pr0)     = make_float4(e0[0], e0[1], e0[2], e0[3]);
            *(float4*)(pr0 + 4) = make_float4(e0[4], e0[5], e0[6], e0[7]);
            *(float4*)(pr1)     = make_float4(e1[0], e1[1], e1[2], e1[3]);
            *(float4*)(pr1 + 4) = make_float4(e1[4], e1[5], e1[6], e1[7]);
            if (write_aw) {
                float4* dA = (float4*)(aw + ((size_t)bh * LSEQ + iA) * LSEQ + j0 + 8 * tx);
                float4* dB = (float4*)(aw + ((size_t)bh * LSEQ + iB) * LSEQ + j0 + 8 * tx);
                dA[0] = make_float4(e0[0], e0[1], e0[2], e0[3]);
                dA[1] = make_float4(e0[4], e0[5], e0[6], e0[7]);
                dB[0] = make_float4(e1[0], e1[1], e1[2], e1[3]);
                dB[1] = make_float4(e1[4], e1[5], e1[6], e1[7]);
            }
        }
        __syncthreads();   // Ps written; KT/WT reads done

        // ---- PV fills: VS[j][dd], WV[s][dd] ----
        const float* vbase = vh + ((size_t)bh * LSEQ + j0) * DH;
#pragma unroll
        for (int k = 0; k < 4; k++) {
            int idx = tid + k * 512;
            int j = idx >> 4, dd4 = idx & 15;
            *(float4*)(VS + j * 68 + dd4 * 4) =
                *(const float4*)(vbase + j * 64 + dd4 * 4);
        }
#pragma unroll
        for (int k = 0; k < 8; k++) {
            int idx = tid + k * 512;
            int s = idx >> 4, dd4 = idx & 15;
            int delta = s + D0;
            float4 tt = make_float4(0.f, 0.f, 0.f, 0.f);
            if (delta >= 0 && delta < LSEQ)
                tt = *(const float4*)(val_rel + (size_t)(LSEQ - 1 - delta) * DH + dd4 * 4);
            *(float4*)(WV + s * 68 + dd4 * 4) = tt;
        }
        __syncthreads();

        // ---- PV: Co[u][cc] += p * (V + W), 4-slot register sliding window ----
        ull wr[4][2];
#pragma unroll
        for (int u = 0; u < 4; u++) {
            int r = 127 + 4 * ty + u;
            wr[u][0] = *(const ull*)(WV + r * 68 + 2 * tx);
            wr[u][1] = *(const ull*)(WV + r * 68 + 32 + 2 * tx);
        }

        for (int jb = 0; jb < 128; jb += 8) {
#pragma unroll
            for (int js = 0; js < 8; js++) {
                const int jj = jb + js;
                ull v0 = *(const ull*)(VS + jj * 68 + 2 * tx);
                ull v1 = *(const ull*)(VS + jj * 68 + 32 + 2 * tx);
#pragma unroll
                for (int u = 0; u < 4; u++) {
                    ull pd = dup2(Ps[(4 * ty + u) * 132 + jj]);
                    const int sl = (u - js) & 3;
                    Co[u][0] = fma2(pd, add2(v0, wr[sl][0]), Co[u][0]);
                    Co[u][1] = fma2(pd, add2(v1, wr[sl][1]), Co[u][1]);
                }
                const int rn = 126 + 4 * ty - jj;
                const int sln = (-(js + 1)) & 3;
                if (rn >= 0) {
                    wr[sln][0] = *(const ull*)(WV + rn * 68 + 2 * tx);
                    wr[sln][1] = *(const ull*)(WV + rn * 68 + 32 + 2 * tx);
                } else {
                    wr[sln][0] = 0; wr[sln][1] = 0;
                }
            }
        }
    }

    // ---- finalize ----
#pragma unroll
    for (int u = 0; u < 4; u++) {
#pragma unroll
        for (int o = 8; o > 0; o >>= 1)
            rs[u] += __shfl_xor_sync(0xffffffffu, rs[u], o);
    }

    const int b = bh >> 3, h = bh & 7;
#pragma unroll
    for (int u = 0; u < 4; u++) {
        const int i = i0 + 4 * ty + u;
        const float inv = 1.0f / rs[u];
        if (tx == 0) rowsum[bh * LSEQ + i] = rs[u];
        ull invd = dup2(inv);
        float* base = att + ((size_t)(b * LSEQ + i)) * DMODEL + h * DH;
        *(ull*)(base + 2 * tx)      = mul2(Co[u][0], invd);
        *(ull*)(base + 32 + 2 * tx) = mul2(Co[u][1], invd);
    }
}

// ---------------------------------------------------------------------------
__global__ __launch_bounds__(256) void norm_aw(float* __restrict__ aw,
                                               const float* __restrict__ rowsum)
{
    const int row = blockIdx.x;
    const int i = row & (LSEQ - 1);
    const float inv = 1.0f / rowsum[row];
    float4* p = (float4*)(aw + (size_t)row * LSEQ);
#pragma unroll
    for (int k = 0; k < 2; k++) {
        int c4 = threadIdx.x + k * 256;
        int j = c4 * 4;
        float4 v;
        if (j + 3 <= i) {
            v = p[c4];
            v.x *= inv; v.y *= inv; v.z *= inv; v.w *= inv;
        } else if (j > i) {
            v = make_float4(0.f, 0.f, 0.f, 0.f);
        } else {
            v = p[c4];
            v.x = (j     <= i) ? v.x * inv : 0.f;
            v.y = (j + 1 <= i) ? v.y * inv : 0.f;
            v.z = (j + 2 <= i) ? v.z * inv : 0.f;
            v.w = (j + 3 <= i) ? v.w * inv : 0.f;
        }
        p[c4] = v;
    }
}

// ---------------------------------------------------------------------------
extern "C" void kernel_launch(void* const* d_in, const int* in_sizes, int n_in,
                              void* d_out, int out_size)
{
    const float* q       = (const float*)d_in[0];
    const float* k       = (const float*)d_in[1];
    const float* v       = (const float*)d_in[2];
    const float* wq      = (const float*)d_in[4];
    const float* bq      = (const float*)d_in[5];
    const float* wk      = (const float*)d_in[6];
    const float* bk      = (const float*)d_in[7];
    const float* wv      = (const float*)d_in[8];
    const float* bv      = (const float*)d_in[9];
    const float* wo      = (const float*)d_in[10];
    const float* bo      = (const float*)d_in[11];
    const float* key_rel = (const float*)d_in[12];
    const float* val_rel = (const float*)d_in[13];

    float* out = (float*)d_out;
    const long long OUT_ELEMS = (long long)BATCH * LSEQ * DMODEL;
    const long long AW_ELEMS  = (long long)BH * LSEQ * LSEQ;
    const int write_aw = ((long long)out_size >= OUT_ELEMS + AW_ELEMS) ? 1 : 0;
    float* aw = out + OUT_ELEMS;

    float *qh = nullptr, *kh = nullptr, *vh = nullptr, *att = nullptr, *rsum = nullptr;
    cudaGetSymbolAddress((void**)&qh,   g_qh);
    cudaGetSymbolAddress((void**)&kh,   g_kh);
    cudaGetSymbolAddress((void**)&vh,   g_vh);
    cudaGetSymbolAddress((void**)&att,  g_att);
    cudaGetSymbolAddress((void**)&rsum, g_rowsum);

    cudaFuncSetAttribute(attn_kernel, cudaFuncAttributeMaxDynamicSharedMemorySize, SMEM_BYTES);

    // fused Q/K/V projections (z = 0,1,2)
    dim3 gGrid3(MROWS / 64, DMODEL / 64, 3);
    gemm512<<<gGrid3, 256>>>(q, wq, bq, qh,
                             k, wk, bk, kh,
                             v, wv, bv, vh, 1);

    dim3 aGrid(LSEQ / 128, BH);
    attn_kernel<<<aGrid, 512, SMEM_BYTES>>>(qh, kh, vh, key_rel, val_rel,
                                            aw, att, rsum, write_aw);
    if (write_aw)
        norm_aw<<<BH * LSEQ, 256>>>(aw, rsum);

    dim3 gGrid(MROWS / 64, DMODEL / 64, 1);
    gemm512<<<gGrid, 256>>>(att, wo, bo, out,
                            att, wo, bo, out,
                            att, wo, bo, out, 0);
}

// round 6
// speedup vs baseline: 1.1197x; 1.1197x over previous
#include <cuda_runtime.h>

#define LSEQ   2048
#define DMODEL 512
#define NHEAD  8
#define DH     64
#define BATCH  2
#define BH     (BATCH * NHEAD)   /* 16 */
#define MROWS  (BATCH * LSEQ)    /* 4096 */
#define SHIFT  48.0f

typedef unsigned long long ull;

// ---------------- packed f32x2 helpers ----------------
__device__ __forceinline__ ull pack2(float lo, float hi) {
    ull r; asm("mov.b64 %0, {%1, %2};" : "=l"(r) : "f"(lo), "f"(hi)); return r;
}
__device__ __forceinline__ ull dup2(float x) {
    ull r; asm("mov.b64 %0, {%1, %1};" : "=l"(r) : "f"(x)); return r;
}
__device__ __forceinline__ void unpack2(ull v, float& lo, float& hi) {
    asm("mov.b64 {%0, %1}, %2;" : "=f"(lo), "=f"(hi) : "l"(v));
}
__device__ __forceinline__ ull fma2(ull a, ull b, ull c) {
    ull d; asm("fma.rn.f32x2 %0, %1, %2, %3;" : "=l"(d) : "l"(a), "l"(b), "l"(c)); return d;
}
__device__ __forceinline__ ull add2(ull a, ull b) {
    ull d; asm("add.rn.f32x2 %0, %1, %2;" : "=l"(d) : "l"(a), "l"(b)); return d;
}
__device__ __forceinline__ ull mul2(ull a, ull b) {
    ull d; asm("mul.rn.f32x2 %0, %1, %2;" : "=l"(d) : "l"(a), "l"(b)); return d;
}

// ---------------- scratch ----------------
__device__ float g_qh[BH * LSEQ * DH];
__device__ float g_kh[BH * LSEQ * DH];
__device__ float g_vh[BH * LSEQ * DH];
__device__ float g_att[MROWS * DMODEL];
__device__ float g_rowsum[BH * LSEQ];

// ---------------------------------------------------------------------------
// 64x64-tiled GEMM with f32x2 inner math: C[4096,512] = A @ W + bias
// head_layout=1: blockIdx.z selects (q,k,v); writes head layout.
// ---------------------------------------------------------------------------
__global__ __launch_bounds__(256) void gemm512(const float* __restrict__ A0,
                                               const float* __restrict__ W0,
                                               const float* __restrict__ b0,
                                               float* __restrict__ o0,
                                               const float* __restrict__ A1,
                                               const float* __restrict__ W1,
                                               const float* __restrict__ b1,
                                               float* __restrict__ o1,
                                               const float* __restrict__ A2,
                                               const float* __restrict__ W2,
                                               const float* __restrict__ b2,
                                               float* __restrict__ o2,
                                               int head_layout)
{
    const float* A = A0; const float* W = W0; const float* bias = b0; float* out = o0;
    if (blockIdx.z == 1) { A = A1; W = W1; bias = b1; out = o1; }
    if (blockIdx.z == 2) { A = A2; W = W2; bias = b2; out = o2; }

    __shared__ float As[64 * 16];
    __shared__ float Ws[16 * 64];
    const int tid = threadIdx.x;
    const int tx = tid & 15, ty = tid >> 4;
    const int m0 = blockIdx.x * 64;
    const int n0 = blockIdx.y * 64;

    ull acc2[4][2] = {};

    for (int k0 = 0; k0 < DMODEL; k0 += 16) {
        {
            int idx = tid * 4;
            int r = idx >> 4, c = idx & 15;
            *(float4*)(As + idx) =
                *(const float4*)(A + (size_t)(m0 + r) * DMODEL + k0 + c);
            int kk = idx >> 6, cc = idx & 63;
            *(float4*)(Ws + idx) =
                *(const float4*)(W + (size_t)(k0 + kk) * DMODEL + n0 + cc);
        }
        __syncthreads();
#pragma unroll
        for (int kk = 0; kk < 16; kk++) {
            ulonglong2 bp = *(const ulonglong2*)(Ws + kk * 64 + tx * 4);
#pragma unroll
            for (int u = 0; u < 4; u++) {
                ull ad = dup2(As[(ty * 4 + u) * 16 + kk]);
                acc2[u][0] = fma2(ad, bp.x, acc2[u][0]);
                acc2[u][1] = fma2(ad, bp.y, acc2[u][1]);
            }
        }
        __syncthreads();
    }

    float4 bb = *(const float4*)(bias + n0 + tx * 4);

#pragma unroll
    for (int u = 0; u < 4; u++) {
        int m = m0 + ty * 4 + u;
        float4 o;
        unpack2(acc2[u][0], o.x, o.y);
        unpack2(acc2[u][1], o.z, o.w);
        o.x += bb.x; o.y += bb.y; o.z += bb.z; o.w += bb.w;
        if (head_layout) {
            int b = m >> 11;
            int l = m & (LSEQ - 1);
            int h = n0 >> 6;
            float* p = out + (((size_t)(b * NHEAD + h) * LSEQ + l) * DH + tx * 4);
            *(float4*)p = o;
        } else {
            *(float4*)(out + (size_t)m * DMODEL + n0 + tx * 4) = o;
        }
    }
}

// ---------------------------------------------------------------------------
// Fused causal attention, f32x2 math, 256 threads, 8x8 frags, 128x128 tiles.
// S phase split into two d-loop passes (QK then rel) to keep live registers
// under the spill threshold (R4 ran at 255 regs with local spills).
// ---------------------------------------------------------------------------
#define QT_OFF 0
#define KB_OFF 8448
#define WB_OFF 17152
#define PS_OFF 34560
#define SMEM_FLOATS 51456
#define SMEM_BYTES (SMEM_FLOATS * 4)

__global__ __launch_bounds__(256, 1) void attn_kernel(const float* __restrict__ qh,
                                                      const float* __restrict__ kh,
                                                      const float* __restrict__ vh,
                                                      const float* __restrict__ key_rel,
                                                      const float* __restrict__ val_rel,
                                                      float* __restrict__ aw,
                                                      float* __restrict__ att,
                                                      float* __restrict__ rowsum,
                                                      int write_aw)
{
    extern __shared__ float sm[];
    float* QT = sm + QT_OFF;
    float* KT = sm + KB_OFF;   // aliases VS
    float* VS = sm + KB_OFF;
    float* WT = sm + WB_OFF;   // aliases WV
    float* WV = sm + WB_OFF;
    float* Ps = sm + PS_OFF;

    const int tid = threadIdx.x;
    const int tx = tid & 15, ty = tid >> 4;
    const int ib = 15 - blockIdx.x;       // heavy blocks first
    const int i0 = ib * 128;
    const int bh = blockIdx.y;
    const int ntiles = ib + 1;

    // ---- QT fill (transpose): QT[d][i] ----
    const float* qbase = qh + ((size_t)bh * LSEQ + i0) * DH;
#pragma unroll
    for (int k = 0; k < 8; k++) {
        int idx = tid + k * 256;          // 2048 float4 groups
        int i = idx & 127, d4 = idx >> 7;
        float4 t = *(const float4*)(qbase + i * 64 + d4 * 4);
        QT[(4 * d4 + 0) * 132 + i] = t.x;
        QT[(4 * d4 + 1) * 132 + i] = t.y;
        QT[(4 * d4 + 2) * 132 + i] = t.z;
        QT[(4 * d4 + 3) * 132 + i] = t.w;
    }

    float rs[8];
    ull Co[8][2];
#pragma unroll
    for (int u = 0; u < 8; u++) { rs[u] = 0.f; Co[u][0] = 0; Co[u][1] = 0; }

    for (int t = 0; t < ntiles; t++) {
        const int j0 = t * 128;
        const int D0 = i0 - j0 - 127;

        __syncthreads();   // prior PV reads done (and QT fill on first iter)

        // ---- KT fill (transpose) ----
        const float* kbase = kh + ((size_t)bh * LSEQ + j0) * DH;
#pragma unroll
        for (int k = 0; k < 8; k++) {
            int idx = tid + k * 256;
            int j = idx & 127, d4 = idx >> 7;
            float4 tt = *(const float4*)(kbase + j * 64 + d4 * 4);
            KT[(4 * d4 + 0) * 132 + j] = tt.x;
            KT[(4 * d4 + 1) * 132 + j] = tt.y;
            KT[(4 * d4 + 2) * 132 + j] = tt.z;
            KT[(4 * d4 + 3) * 132 + j] = tt.w;
        }
        // ---- WT fill: WT[d][si], si = s+1, delta = si-1+D0 ----
#pragma unroll
        for (int k = 0; k < 16; k++) {
            int idx = tid + k * 256;      // 0..4095
            int si = idx & 255, d4 = idx >> 8;
            int delta = si - 1 + D0;
            float4 tt = make_float4(0.f, 0.f, 0.f, 0.f);
            if (delta >= 0 && delta < LSEQ)
                tt = *(const float4*)(key_rel + (size_t)(LSEQ - 1 - delta) * DH + d4 * 4);
            WT[(4 * d4 + 0) * 260 + si] = tt.x;
            WT[(4 * d4 + 1) * 260 + si] = tt.y;
            WT[(4 * d4 + 2) * 260 + si] = tt.z;
            WT[(4 * d4 + 3) * 260 + si] = tt.w;
        }
        __syncthreads();

        ull Sp[4][8] = {};

        // ---- S pass A: Q.K (low register pressure) ----
        {
            const float* qp = QT + 8 * ty;
            const float* kp = KT + 8 * tx;
#pragma unroll 2
            for (int d = 0; d < 64; d++) {
                ulonglong2 aL = *(const ulonglong2*)qp;
                ulonglong2 aH = *(const ulonglong2*)(qp + 4);
                ull ap[4] = { aL.x, aL.y, aH.x, aH.y };

                float4 b0 = *(const float4*)kp;
                float4 b1 = *(const float4*)(kp + 4);
                ull bd[8] = { dup2(b0.x), dup2(b0.y), dup2(b0.z), dup2(b0.w),
                              dup2(b1.x), dup2(b1.y), dup2(b1.z), dup2(b1.w) };
#pragma unroll
                for (int uu = 0; uu < 4; uu++)
#pragma unroll
                    for (int v = 0; v < 8; v++)
                        Sp[uu][v] = fma2(ap[uu], bd[v], Sp[uu][v]);
                qp += 132; kp += 132;
            }
        }

        // ---- S pass B: Q.key_rel window ----
        {
            const float* qp = QT + 8 * ty;
            const float* wp = WT + (120 + 8 * ty - 8 * tx);
#pragma unroll 2
            for (int d = 0; d < 64; d++) {
                ulonglong2 aL = *(const ulonglong2*)qp;
                ulonglong2 aH = *(const ulonglong2*)(qp + 4);
                ull ap[4] = { aL.x, aL.y, aH.x, aH.y };

                float4 w0 = *(const float4*)wp;
                float4 w1 = *(const float4*)(wp + 4);
                float4 w2 = *(const float4*)(wp + 8);
                float4 w3 = *(const float4*)(wp + 12);
                float wv[16] = { w0.x, w0.y, w0.z, w0.w, w1.x, w1.y, w1.z, w1.w,
                                 w2.x, w2.y, w2.z, w2.w, w3.x, w3.y, w3.z, w3.w };
                ull P[14];
#pragma unroll
                for (int o = 1; o <= 14; o++) P[o - 1] = pack2(wv[o], wv[o + 1]);

#pragma unroll
                for (int uu = 0; uu < 4; uu++)
#pragma unroll
                    for (int v = 0; v < 8; v++)
                        Sp[uu][v] = fma2(ap[uu], P[7 + 2 * uu - v], Sp[uu][v]);
                qp += 132; wp += 260;
            }
        }

        // ---- exp, mask, rowsum, Ps + aw stores ----
#pragma unroll
        for (int uu = 0; uu < 4; uu++) {
            const int iA = i0 + 8 * ty + 2 * uu;
            const int iB = iA + 1;
            float e0[8], e1[8];
#pragma unroll
            for (int v = 0; v < 8; v++) {
                float sA, sB;
                unpack2(Sp[uu][v], sA, sB);
                const int j = j0 + 8 * tx + v;
                e0[v] = (j <= iA) ? __expf(sA - SHIFT) : 0.f;
                e1[v] = (j <= iB) ? __expf(sB - SHIFT) : 0.f;
                rs[2 * uu]     += e0[v];
                rs[2 * uu + 1] += e1[v];
            }
            float* pr0 = Ps + (8 * ty + 2 * uu) * 132 + 8 * tx;
            float* pr1 = pr0 + 132;
            *(float4*)(pr0)     = make_float4(e0[0], e0[1], e0[2], e0[3]);
            *(float4*)(pr0 + 4) = make_float4(e0[4], e0[5], e0[6], e0[7]);
            *(float4*)(pr1)     = make_float4(e1[0], e1[1], e1[2], e1[3]);
            *(float4*)(pr1 + 4) = make_float4(e1[4], e1[5], e1[6], e1[7]);
            if (write_aw) {
                float4* dA = (float4*)(aw + ((size_t)bh * LSEQ + iA) * LSEQ + j0 + 8 * tx);
                float4* dB = (float4*)(aw + ((size_t)bh * LSEQ + iB) * LSEQ + j0 + 8 * tx);
                dA[0] = make_float4(e0[0], e0[1], e0[2], e0[3]);
                dA[1] = make_float4(e0[4], e0[5], e0[6], e0[7]);
                dB[0] = make_float4(e1[0], e1[1], e1[2], e1[3]);
                dB[1] = make_float4(e1[4], e1[5], e1[6], e1[7]);
            }
        }
        __syncthreads();   // Ps written; KT/WT reads done

        // ---- PV fills: VS[j][dd], WV[s][dd] ----
        const float* vbase = vh + ((size_t)bh * LSEQ + j0) * DH;
#pragma unroll
        for (int k = 0; k < 8; k++) {
            int idx = tid + k * 256;
            int j = idx >> 4, dd4 = idx & 15;
            *(float4*)(VS + j * 68 + dd4 * 4) =
                *(const float4*)(vbase + j * 64 + dd4 * 4);
        }
#pragma unroll
        for (int k = 0; k < 16; k++) {
            int idx = tid + k * 256;
            int s = idx >> 4, dd4 = idx & 15;
            int delta = s + D0;
            float4 tt = make_float4(0.f, 0.f, 0.f, 0.f);
            if (delta >= 0 && delta < LSEQ)
                tt = *(const float4*)(val_rel + (size_t)(LSEQ - 1 - delta) * DH + dd4 * 4);
            *(float4*)(WV + s * 68 + dd4 * 4) = tt;
        }
        __syncthreads();

        // ---- PV: Co[u][cc] += p * (V + W), 8-slot register sliding window ----
        ull wr[8][2];
#pragma unroll
        for (int u = 0; u < 8; u++) {
            int r = 127 + 8 * ty + u;
            wr[u][0] = *(const ull*)(WV + r * 68 + 2 * tx);
            wr[u][1] = *(const ull*)(WV + r * 68 + 32 + 2 * tx);
        }

        for (int jb = 0; jb < 128; jb += 8) {
#pragma unroll
            for (int js = 0; js < 8; js++) {
                const int jj = jb + js;
                ull v0 = *(const ull*)(VS + jj * 68 + 2 * tx);
                ull v1 = *(const ull*)(VS + jj * 68 + 32 + 2 * tx);
#pragma unroll
                for (int u = 0; u < 8; u++) {
                    ull pd = dup2(Ps[(8 * ty + u) * 132 + jj]);
                    const int sl = (u - js) & 7;
                    Co[u][0] = fma2(pd, add2(v0, wr[sl][0]), Co[u][0]);
                    Co[u][1] = fma2(pd, add2(v1, wr[sl][1]), Co[u][1]);
                }
                const int rn = 126 + 8 * ty - jj;
                const int sln = (-(js + 1)) & 7;
                if (rn >= 0) {
                    wr[sln][0] = *(const ull*)(WV + rn * 68 + 2 * tx);
                    wr[sln][1] = *(const ull*)(WV + rn * 68 + 32 + 2 * tx);
                } else {
                    wr[sln][0] = 0; wr[sln][1] = 0;
                }
            }
        }
    }

    // ---- finalize ----
#pragma unroll
    for (int u = 0; u < 8; u++) {
#pragma unroll
        for (int o = 8; o > 0; o >>= 1)
            rs[u] += __shfl_xor_sync(0xffffffffu, rs[u], o);
    }

    const int b = bh >> 3, h = bh & 7;
#pragma unroll
    for (int u = 0; u < 8; u++) {
        const int i = i0 + 8 * ty + u;
        const float inv = 1.0f / rs[u];
        if (tx == 0) rowsum[bh * LSEQ + i] = rs[u];
        ull invd = dup2(inv);
        float* base = att + ((size_t)(b * LSEQ + i)) * DMODEL + h * DH;
        *(ull*)(base + 2 * tx)      = mul2(Co[u][0], invd);
        *(ull*)(base + 32 + 2 * tx) = mul2(Co[u][1], invd);
    }
}

// ---------------------------------------------------------------------------
__global__ __launch_bounds__(256) void norm_aw(float* __restrict__ aw,
                                               const float* __restrict__ rowsum)
{
    const int row = blockIdx.x;
    const int i = row & (LSEQ - 1);
    const float inv = 1.0f / rowsum[row];
    float4* p = (float4*)(aw + (size_t)row * LSEQ);
#pragma unroll
    for (int k = 0; k < 2; k++) {
        int c4 = threadIdx.x + k * 256;
        int j = c4 * 4;
        float4 v;
        if (j + 3 <= i) {
            v = p[c4];
            v.x *= inv; v.y *= inv; v.z *= inv; v.w *= inv;
        } else if (j > i) {
            v = make_float4(0.f, 0.f, 0.f, 0.f);
        } else {
            v = p[c4];
            v.x = (j     <= i) ? v.x * inv : 0.f;
            v.y = (j + 1 <= i) ? v.y * inv : 0.f;
            v.z = (j + 2 <= i) ? v.z * inv : 0.f;
            v.w = (j + 3 <= i) ? v.w * inv : 0.f;
        }
        p[c4] = v;
    }
}

// ---------------------------------------------------------------------------
extern "C" void kernel_launch(void* const* d_in, const int* in_sizes, int n_in,
                              void* d_out, int out_size)
{
    const float* q       = (const float*)d_in[0];
    const float* k       = (const float*)d_in[1];
    const float* v       = (const float*)d_in[2];
    const float* wq      = (const float*)d_in[4];
    const float* bq      = (const float*)d_in[5];
    const float* wk      = (const float*)d_in[6];
    const float* bk      = (const float*)d_in[7];
    const float* wv      = (const float*)d_in[8];
    const float* bv      = (const float*)d_in[9];
    const float* wo      = (const float*)d_in[10];
    const float* bo      = (const float*)d_in[11];
    const float* key_rel = (const float*)d_in[12];
    const float* val_rel = (const float*)d_in[13];

    float* out = (float*)d_out;
    const long long OUT_ELEMS = (long long)BATCH * LSEQ * DMODEL;
    const long long AW_ELEMS  = (long long)BH * LSEQ * LSEQ;
    const int write_aw = ((long long)out_size >= OUT_ELEMS + AW_ELEMS) ? 1 : 0;
    float* aw = out + OUT_ELEMS;

    float *qh = nullptr, *kh = nullptr, *vh = nullptr, *att = nullptr, *rsum = nullptr;
    cudaGetSymbolAddress((void**)&qh,   g_qh);
    cudaGetSymbolAddress((void**)&kh,   g_kh);
    cudaGetSymbolAddress((void**)&vh,   g_vh);
    cudaGetSymbolAddress((void**)&att,  g_att);
    cudaGetSymbolAddress((void**)&rsum, g_rowsum);

    cudaFuncSetAttribute(attn_kernel, cudaFuncAttributeMaxDynamicSharedMemorySize, SMEM_BYTES);

    // fused Q/K/V projections (z = 0,1,2)
    dim3 gGrid3(MROWS / 64, DMODEL / 64, 3);
    gemm512<<<gGrid3, 256>>>(q, wq, bq, qh,
                             k, wk, bk, kh,
                             v, wv, bv, vh, 1);

    dim3 aGrid(LSEQ / 128, BH);
    attn_kernel<<<aGrid, 256, SMEM_BYTES>>>(qh, kh, vh, key_rel, val_rel,
                                            aw, att, rsum, write_aw);
    if (write_aw)
        norm_aw<<<BH * LSEQ, 256>>>(aw, rsum);

    dim3 gGrid(MROWS / 64, DMODEL / 64, 1);
    gemm512<<<gGrid, 256>>>(att, wo, bo, out,
                            att, wo, bo, out,
                            att, wo, bo, out, 0);
}

// round 7
// speedup vs baseline: 1.1208x; 1.0010x over previous
#include <cuda_runtime.h>

#define LSEQ   2048
#define DMODEL 512
#define NHEAD  8
#define DH     64
#define BATCH  2
#define BH     (BATCH * NHEAD)   /* 16 */
#define MROWS  (BATCH * LSEQ)    /* 4096 */
#define SHIFT  48.0f

typedef unsigned long long ull;

// ---------------- packed f32x2 helpers ----------------
__device__ __forceinline__ ull pack2(float lo, float hi) {
    ull r; asm("mov.b64 %0, {%1, %2};" : "=l"(r) : "f"(lo), "f"(hi)); return r;
}
__device__ __forceinline__ ull dup2(float x) {
    ull r; asm("mov.b64 %0, {%1, %1};" : "=l"(r) : "f"(x)); return r;
}
__device__ __forceinline__ void unpack2(ull v, float& lo, float& hi) {
    asm("mov.b64 {%0, %1}, %2;" : "=f"(lo), "=f"(hi) : "l"(v));
}
__device__ __forceinline__ ull fma2(ull a, ull b, ull c) {
    ull d; asm("fma.rn.f32x2 %0, %1, %2, %3;" : "=l"(d) : "l"(a), "l"(b), "l"(c)); return d;
}
__device__ __forceinline__ ull add2(ull a, ull b) {
    ull d; asm("add.rn.f32x2 %0, %1, %2;" : "=l"(d) : "l"(a), "l"(b)); return d;
}
__device__ __forceinline__ ull mul2(ull a, ull b) {
    ull d; asm("mul.rn.f32x2 %0, %1, %2;" : "=l"(d) : "l"(a), "l"(b)); return d;
}

// ---------------- scratch ----------------
__device__ float g_qh[BH * LSEQ * DH];
__device__ float g_kh[BH * LSEQ * DH];
__device__ float g_vh[BH * LSEQ * DH];
__device__ float g_att[MROWS * DMODEL];
__device__ float g_rowsum[BH * LSEQ];

// ---------------------------------------------------------------------------
// 64x64-tiled GEMM with f32x2 inner math: C[4096,512] = A @ W + bias
// ---------------------------------------------------------------------------
__global__ __launch_bounds__(256) void gemm512(const float* __restrict__ A0,
                                               const float* __restrict__ W0,
                                               const float* __restrict__ b0,
                                               float* __restrict__ o0,
                                               const float* __restrict__ A1,
                                               const float* __restrict__ W1,
                                               const float* __restrict__ b1,
                                               float* __restrict__ o1,
                                               const float* __restrict__ A2,
                                               const float* __restrict__ W2,
                                               const float* __restrict__ b2,
                                               float* __restrict__ o2,
                                               int head_layout)
{
    const float* A = A0; const float* W = W0; const float* bias = b0; float* out = o0;
    if (blockIdx.z == 1) { A = A1; W = W1; bias = b1; out = o1; }
    if (blockIdx.z == 2) { A = A2; W = W2; bias = b2; out = o2; }

    __shared__ float As[64 * 16];
    __shared__ float Ws[16 * 64];
    const int tid = threadIdx.x;
    const int tx = tid & 15, ty = tid >> 4;
    const int m0 = blockIdx.x * 64;
    const int n0 = blockIdx.y * 64;

    ull acc2[4][2] = {};

    for (int k0 = 0; k0 < DMODEL; k0 += 16) {
        {
            int idx = tid * 4;
            int r = idx >> 4, c = idx & 15;
            *(float4*)(As + idx) =
                *(const float4*)(A + (size_t)(m0 + r) * DMODEL + k0 + c);
            int kk = idx >> 6, cc = idx & 63;
            *(float4*)(Ws + idx) =
                *(const float4*)(W + (size_t)(k0 + kk) * DMODEL + n0 + cc);
        }
        __syncthreads();
#pragma unroll
        for (int kk = 0; kk < 16; kk++) {
            ulonglong2 bp = *(const ulonglong2*)(Ws + kk * 64 + tx * 4);
#pragma unroll
            for (int u = 0; u < 4; u++) {
                ull ad = dup2(As[(ty * 4 + u) * 16 + kk]);
                acc2[u][0] = fma2(ad, bp.x, acc2[u][0]);
                acc2[u][1] = fma2(ad, bp.y, acc2[u][1]);
            }
        }
        __syncthreads();
    }

    float4 bb = *(const float4*)(bias + n0 + tx * 4);

#pragma unroll
    for (int u = 0; u < 4; u++) {
        int m = m0 + ty * 4 + u;
        float4 o;
        unpack2(acc2[u][0], o.x, o.y);
        unpack2(acc2[u][1], o.z, o.w);
        o.x += bb.x; o.y += bb.y; o.z += bb.z; o.w += bb.w;
        if (head_layout) {
            int b = m >> 11;
            int l = m & (LSEQ - 1);
            int h = n0 >> 6;
            float* p = out + (((size_t)(b * NHEAD + h) * LSEQ + l) * DH + tx * 4);
            *(float4*)p = o;
        } else {
            *(float4*)(out + (size_t)m * DMODEL + n0 + tx * 4) = o;
        }
    }
}

// ---------------------------------------------------------------------------
// Fused causal attention, f32x2 math, 256 threads, 8x8 frags, 128x128 tiles.
// S phase: two d-loop passes (QK unroll-4 pipelined, rel unroll-2).
// PV phase: 4-jj batched loads (float4 p, prefetched V) for MLP.
// ---------------------------------------------------------------------------
#define QT_OFF 0
#define KB_OFF 8448
#define WB_OFF 17152
#define PS_OFF 34560
#define SMEM_FLOATS 51456
#define SMEM_BYTES (SMEM_FLOATS * 4)

__global__ __launch_bounds__(256, 1) void attn_kernel(const float* __restrict__ qh,
                                                      const float* __restrict__ kh,
                                                      const float* __restrict__ vh,
                                                      const float* __restrict__ key_rel,
                                                      const float* __restrict__ val_rel,
                                                      float* __restrict__ aw,
                                                      float* __restrict__ att,
                                                      float* __restrict__ rowsum,
                                                      int write_aw)
{
    extern __shared__ float sm[];
    float* QT = sm + QT_OFF;
    float* KT = sm + KB_OFF;   // aliases VS
    float* VS = sm + KB_OFF;
    float* WT = sm + WB_OFF;   // aliases WV
    float* WV = sm + WB_OFF;
    float* Ps = sm + PS_OFF;

    const int tid = threadIdx.x;
    const int tx = tid & 15, ty = tid >> 4;
    const int ib = 15 - blockIdx.x;       // heavy blocks first
    const int i0 = ib * 128;
    const int bh = blockIdx.y;
    const int ntiles = ib + 1;

    // ---- QT fill (transpose): QT[d][i] ----
    const float* qbase = qh + ((size_t)bh * LSEQ + i0) * DH;
#pragma unroll
    for (int k = 0; k < 8; k++) {
        int idx = tid + k * 256;
        int i = idx & 127, d4 = idx >> 7;
        float4 t = *(const float4*)(qbase + i * 64 + d4 * 4);
        QT[(4 * d4 + 0) * 132 + i] = t.x;
        QT[(4 * d4 + 1) * 132 + i] = t.y;
        QT[(4 * d4 + 2) * 132 + i] = t.z;
        QT[(4 * d4 + 3) * 132 + i] = t.w;
    }

    float rs[8];
    ull Co[8][2];
#pragma unroll
    for (int u = 0; u < 8; u++) { rs[u] = 0.f; Co[u][0] = 0; Co[u][1] = 0; }

    for (int t = 0; t < ntiles; t++) {
        const int j0 = t * 128;
        const int D0 = i0 - j0 - 127;

        __syncthreads();   // prior PV reads done (and QT fill on first iter)

        // ---- KT fill (transpose) ----
        const float* kbase = kh + ((size_t)bh * LSEQ + j0) * DH;
#pragma unroll
        for (int k = 0; k < 8; k++) {
            int idx = tid + k * 256;
            int j = idx & 127, d4 = idx >> 7;
            float4 tt = *(const float4*)(kbase + j * 64 + d4 * 4);
            KT[(4 * d4 + 0) * 132 + j] = tt.x;
            KT[(4 * d4 + 1) * 132 + j] = tt.y;
            KT[(4 * d4 + 2) * 132 + j] = tt.z;
            KT[(4 * d4 + 3) * 132 + j] = tt.w;
        }
        // ---- WT fill: WT[d][si], si = s+1, delta = si-1+D0 ----
#pragma unroll
        for (int k = 0; k < 16; k++) {
            int idx = tid + k * 256;
            int si = idx & 255, d4 = idx >> 8;
            int delta = si - 1 + D0;
            float4 tt = make_float4(0.f, 0.f, 0.f, 0.f);
            if (delta >= 0 && delta < LSEQ)
                tt = *(const float4*)(key_rel + (size_t)(LSEQ - 1 - delta) * DH + d4 * 4);
            WT[(4 * d4 + 0) * 260 + si] = tt.x;
            WT[(4 * d4 + 1) * 260 + si] = tt.y;
            WT[(4 * d4 + 2) * 260 + si] = tt.z;
            WT[(4 * d4 + 3) * 260 + si] = tt.w;
        }
        __syncthreads();

        ull Sp[4][8] = {};

        // ---- S pass A: Q.K (unroll 4 for software pipelining) ----
        {
            const float* qp = QT + 8 * ty;
            const float* kp = KT + 8 * tx;
#pragma unroll 4
            for (int d = 0; d < 64; d++) {
                ulonglong2 aL = *(const ulonglong2*)qp;
                ulonglong2 aH = *(const ulonglong2*)(qp + 4);
                ull ap[4] = { aL.x, aL.y, aH.x, aH.y };

                float4 b0 = *(const float4*)kp;
                float4 b1 = *(const float4*)(kp + 4);
                ull bd[8] = { dup2(b0.x), dup2(b0.y), dup2(b0.z), dup2(b0.w),
                              dup2(b1.x), dup2(b1.y), dup2(b1.z), dup2(b1.w) };
#pragma unroll
                for (int uu = 0; uu < 4; uu++)
#pragma unroll
                    for (int v = 0; v < 8; v++)
                        Sp[uu][v] = fma2(ap[uu], bd[v], Sp[uu][v]);
                qp += 132; kp += 132;
            }
        }

        // ---- S pass B: Q.key_rel window ----
        {
            const float* qp = QT + 8 * ty;
            const float* wp = WT + (120 + 8 * ty - 8 * tx);
#pragma unroll 2
            for (int d = 0; d < 64; d++) {
                ulonglong2 aL = *(const ulonglong2*)qp;
                ulonglong2 aH = *(const ulonglong2*)(qp + 4);
                ull ap[4] = { aL.x, aL.y, aH.x, aH.y };

                float4 w0 = *(const float4*)wp;
                float4 w1 = *(const float4*)(wp + 4);
                float4 w2 = *(const float4*)(wp + 8);
                float4 w3 = *(const float4*)(wp + 12);
                float wv[16] = { w0.x, w0.y, w0.z, w0.w, w1.x, w1.y, w1.z, w1.w,
                                 w2.x, w2.y, w2.z, w2.w, w3.x, w3.y, w3.z, w3.w };
                ull P[14];
#pragma unroll
                for (int o = 1; o <= 14; o++) P[o - 1] = pack2(wv[o], wv[o + 1]);

#pragma unroll
                for (int uu = 0; uu < 4; uu++)
#pragma unroll
                    for (int v = 0; v < 8; v++)
                        Sp[uu][v] = fma2(ap[uu], P[7 + 2 * uu - v], Sp[uu][v]);
                qp += 132; wp += 260;
            }
        }

        // ---- exp, mask, rowsum, Ps + aw stores ----
#pragma unroll
        for (int uu = 0; uu < 4; uu++) {
            const int iA = i0 + 8 * ty + 2 * uu;
            const int iB = iA + 1;
            float e0[8], e1[8];
#pragma unroll
            for (int v = 0; v < 8; v++) {
                float sA, sB;
                unpack2(Sp[uu][v], sA, sB);
                const int j = j0 + 8 * tx + v;
                e0[v] = (j <= iA) ? __expf(sA - SHIFT) : 0.f;
                e1[v] = (j <= iB) ? __expf(sB - SHIFT) : 0.f;
                rs[2 * uu]     += e0[v];
                rs[2 * uu + 1] += e1[v];
            }
            float* pr0 = Ps + (8 * ty + 2 * uu) * 132 + 8 * tx;
            float* pr1 = pr0 + 132;
            *(float4*)(pr0)     = make_float4(e0[0], e0[1], e0[2], e0[3]);
            *(float4*)(pr0 + 4) = make_float4(e0[4], e0[5], e0[6], e0[7]);
            *(float4*)(pr1)     = make_float4(e1[0], e1[1], e1[2], e1[3]);
            *(float4*)(pr1 + 4) = make_float4(e1[4], e1[5], e1[6], e1[7]);
            if (write_aw) {
                float4* dA = (float4*)(aw + ((size_t)bh * LSEQ + iA) * LSEQ + j0 + 8 * tx);
                float4* dB = (float4*)(aw + ((size_t)bh * LSEQ + iB) * LSEQ + j0 + 8 * tx);
                dA[0] = make_float4(e0[0], e0[1], e0[2], e0[3]);
                dA[1] = make_float4(e0[4], e0[5], e0[6], e0[7]);
                dB[0] = make_float4(e1[0], e1[1], e1[2], e1[3]);
                dB[1] = make_float4(e1[4], e1[5], e1[6], e1[7]);
            }
        }
        __syncthreads();   // Ps written; KT/WT reads done

        // ---- PV fills: VS[j][dd], WV[s][dd] ----
        const float* vbase = vh + ((size_t)bh * LSEQ + j0) * DH;
#pragma unroll
        for (int k = 0; k < 8; k++) {
            int idx = tid + k * 256;
            int j = idx >> 4, dd4 = idx & 15;
            *(float4*)(VS + j * 68 + dd4 * 4) =
                *(const float4*)(vbase + j * 64 + dd4 * 4);
        }
#pragma unroll
        for (int k = 0; k < 16; k++) {
            int idx = tid + k * 256;
            int s = idx >> 4, dd4 = idx & 15;
            int delta = s + D0;
            float4 tt = make_float4(0.f, 0.f, 0.f, 0.f);
            if (delta >= 0 && delta < LSEQ)
                tt = *(const float4*)(val_rel + (size_t)(LSEQ - 1 - delta) * DH + dd4 * 4);
            *(float4*)(WV + s * 68 + dd4 * 4) = tt;
        }
        __syncthreads();

        // ---- PV: Co[u][cc] += p * (V + W), register sliding window,
        //      4-jj batched prefetch of p (float4) and V (independent LDS) ----
        ull wr[8][2];
#pragma unroll
        for (int u = 0; u < 8; u++) {
            int r = 127 + 8 * ty + u;
            wr[u][0] = *(const ull*)(WV + r * 68 + 2 * tx);
            wr[u][1] = *(const ull*)(WV + r * 68 + 32 + 2 * tx);
        }

        for (int jb = 0; jb < 128; jb += 8) {
#pragma unroll
            for (int half = 0; half < 2; half++) {
                // batched loads: p rows (broadcast-dedup float4) + 4x V pairs
                float4 p4[8];
#pragma unroll
                for (int u = 0; u < 8; u++)
                    p4[u] = *(const float4*)(Ps + (8 * ty + u) * 132 + jb + 4 * half);
                ull v0[4], v1[4];
#pragma unroll
                for (int q = 0; q < 4; q++) {
                    const int jj = jb + 4 * half + q;
                    v0[q] = *(const ull*)(VS + jj * 68 + 2 * tx);
                    v1[q] = *(const ull*)(VS + jj * 68 + 32 + 2 * tx);
                }
#pragma unroll
                for (int q = 0; q < 4; q++) {
                    const int js = 4 * half + q;          // compile-time
                    const int jj = jb + js;
#pragma unroll
                    for (int u = 0; u < 8; u++) {
                        ull pd = dup2(((const float*)&p4[u])[q]);
                        const int sl = (u - js) & 7;
                        Co[u][0] = fma2(pd, add2(v0[q], wr[sl][0]), Co[u][0]);
                        Co[u][1] = fma2(pd, add2(v1[q], wr[sl][1]), Co[u][1]);
                    }
                    const int rn = 126 + 8 * ty - jj;
                    const int sln = (-(js + 1)) & 7;
                    if (rn >= 0) {
                        wr[sln][0] = *(const ull*)(WV + rn * 68 + 2 * tx);
                        wr[sln][1] = *(const ull*)(WV + rn * 68 + 32 + 2 * tx);
                    } else {
                        wr[sln][0] = 0; wr[sln][1] = 0;
                    }
                }
            }
        }
    }

    // ---- finalize ----
#pragma unroll
    for (int u = 0; u < 8; u++) {
#pragma unroll
        for (int o = 8; o > 0; o >>= 1)
            rs[u] += __shfl_xor_sync(0xffffffffu, rs[u], o);
    }

    const int b = bh >> 3, h = bh & 7;
#pragma unroll
    for (int u = 0; u < 8; u++) {
        const int i = i0 + 8 * ty + u;
        const float inv = 1.0f / rs[u];
        if (tx == 0) rowsum[bh * LSEQ + i] = rs[u];
        ull invd = dup2(inv);
        float* base = att + ((size_t)(b * LSEQ + i)) * DMODEL + h * DH;
        *(ull*)(base + 2 * tx)      = mul2(Co[u][0], invd);
        *(ull*)(base + 32 + 2 * tx) = mul2(Co[u][1], invd);
    }
}

// ---------------------------------------------------------------------------
__global__ __launch_bounds__(256) void norm_aw(float* __restrict__ aw,
                                               const float* __restrict__ rowsum)
{
    const int row = blockIdx.x;
    const int i = row & (LSEQ - 1);
    const float inv = 1.0f / rowsum[row];
    float4* p = (float4*)(aw + (size_t)row * LSEQ);
#pragma unroll
    for (int k = 0; k < 2; k++) {
        int c4 = threadIdx.x + k * 256;
        int j = c4 * 4;
        float4 v;
        if (j + 3 <= i) {
            v = p[c4];
            v.x *= inv; v.y *= inv; v.z *= inv; v.w *= inv;
        } else if (j > i) {
            v = make_float4(0.f, 0.f, 0.f, 0.f);
        } else {
            v = p[c4];
            v.x = (j     <= i) ? v.x * inv : 0.f;
            v.y = (j + 1 <= i) ? v.y * inv : 0.f;
            v.z = (j + 2 <= i) ? v.z * inv : 0.f;
            v.w = (j + 3 <= i) ? v.w * inv : 0.f;
        }
        p[c4] = v;
    }
}

// ---------------------------------------------------------------------------
extern "C" void kernel_launch(void* const* d_in, const int* in_sizes, int n_in,
                              void* d_out, int out_size)
{
    const float* q       = (const float*)d_in[0];
    const float* k       = (const float*)d_in[1];
    const float* v       = (const float*)d_in[2];
    const float* wq      = (const float*)d_in[4];
    const float* bq      = (const float*)d_in[5];
    const float* wk      = (const float*)d_in[6];
    const float* bk      = (const float*)d_in[7];
    const float* wv      = (const float*)d_in[8];
    const float* bv      = (const float*)d_in[9];
    const float* wo      = (const float*)d_in[10];
    const float* bo      = (const float*)d_in[11];
    const float* key_rel = (const float*)d_in[12];
    const float* val_rel = (const float*)d_in[13];

    float* out = (float*)d_out;
    const long long OUT_ELEMS = (long long)BATCH * LSEQ * DMODEL;
    const long long AW_ELEMS  = (long long)BH * LSEQ * LSEQ;
    const int write_aw = ((long long)out_size >= OUT_ELEMS + AW_ELEMS) ? 1 : 0;
    float* aw = out + OUT_ELEMS;

    float *qh = nullptr, *kh = nullptr, *vh = nullptr, *att = nullptr, *rsum = nullptr;
    cudaGetSymbolAddress((void**)&qh,   g_qh);
    cudaGetSymbolAddress((void**)&kh,   g_kh);
    cudaGetSymbolAddress((void**)&vh,   g_vh);
    cudaGetSymbolAddress((void**)&att,  g_att);
    cudaGetSymbolAddress((void**)&rsum, g_rowsum);

    cudaFuncSetAttribute(attn_kernel, cudaFuncAttributeMaxDynamicSharedMemorySize, SMEM_BYTES);

    // fused Q/K/V projections (z = 0,1,2)
    dim3 gGrid3(MROWS / 64, DMODEL / 64, 3);
    gemm512<<<gGrid3, 256>>>(q, wq, bq, qh,
                             k, wk, bk, kh,
                             v, wv, bv, vh, 1);

    dim3 aGrid(LSEQ / 128, BH);
    attn_kernel<<<aGrid, 256, SMEM_BYTES>>>(qh, kh, vh, key_rel, val_rel,
                                            aw, att, rsum, write_aw);
    if (write_aw)
        norm_aw<<<BH * LSEQ, 256>>>(aw, rsum);

    dim3 gGrid(MROWS / 64, DMODEL / 64, 1);
    gemm512<<<gGrid, 256>>>(att, wo, bo, out,
                            att, wo, bo, out,
                            att, wo, bo, out, 0);
}